// round 1
// baseline (speedup 1.0000x reference)
#include <cuda_runtime.h>

#define C_DIM 512
#define H_DIM 50
#define W_DIM 75
#define HW_DIM (H_DIM * W_DIM)
#define NROI 512
#define PRE 14

// channels-last scratch copy of the feature map: [H*W, C]
__device__ float g_featT[HW_DIM * C_DIM];

// -------------------------------------------------------------------------
// Tiled transpose: bottom [C, H*W] -> g_featT [H*W, C]
// -------------------------------------------------------------------------
__global__ void transpose_kernel(const float* __restrict__ in) {
    __shared__ float tile[32][33];
    int hw0 = blockIdx.x * 32;
    int c0  = blockIdx.y * 32;
    int tx = threadIdx.x, ty = threadIdx.y;

    #pragma unroll
    for (int j = 0; j < 32; j += 8) {
        int hw = hw0 + tx;
        int c  = c0 + ty + j;
        if (hw < HW_DIM) tile[ty + j][tx] = in[c * HW_DIM + hw];
    }
    __syncthreads();
    #pragma unroll
    for (int j = 0; j < 32; j += 8) {
        int hw = hw0 + ty + j;
        int c  = c0 + tx;
        if (hw < HW_DIM) g_featT[hw * C_DIM + c] = tile[tx][ty + j];
    }
}

// -------------------------------------------------------------------------
// Main kernel: grid (512 rois, 4 channel-quarters), 128 threads (4 warps).
// Warp w handles channels [by*128 + w*32, +32), lane = channel.
// -------------------------------------------------------------------------
__global__ __launch_bounds__(128) void roi_pool_kernel(
    const float* __restrict__ rois, float* __restrict__ out) {

    __shared__ int   sxo0[PRE], sxo1[PRE], syo0[PRE], syo1[PRE];
    __shared__ float swx0[PRE], swx1[PRE], swy0[PRE], swy1[PRE];
    __shared__ __align__(16) float stage[4][32 * 49];

    const int n = blockIdx.x;
    const int t = threadIdx.x;

    // ---- per-ROI corner tables (threads 0..27) ----
    if (t < 2 * PRE) {
        const int axis = (t >= PRE);          // 0 = x, 1 = y
        const int i = axis ? (t - PRE) : t;
        const float lo = rois[n * 5 + (axis ? 2 : 1)] * (1.0f / 16.0f);
        const float hi = rois[n * 5 + (axis ? 4 : 3)] * (1.0f / 16.0f);
        const int D = axis ? H_DIM : W_DIM;

        // replicate reference math exactly
        float s  = (hi - lo) / (float)(D - 1);
        float tt = (lo + hi - (float)(D - 1)) / (float)(D - 1);
        float base = -1.0f + (float)i * (2.0f / 13.0f);
        float g  = s * base + tt;
        float xc = (g + 1.0f) * 0.5f * (float)(D - 1);

        float f0 = floorf(xc);
        int   i0 = (int)f0;
        float w1 = xc - f0;
        float w0 = 1.0f - w1;
        float v0 = (i0 >= 0 && i0 <= D - 1) ? 1.0f : 0.0f;
        float v1 = (i0 + 1 >= 0 && i0 + 1 <= D - 1) ? 1.0f : 0.0f;
        int c0 = min(max(i0, 0), D - 1);
        int c1 = min(max(i0 + 1, 0), D - 1);

        if (axis) {
            syo0[i] = c0 * (W_DIM * C_DIM);
            syo1[i] = c1 * (W_DIM * C_DIM);
            swy0[i] = w0 * v0;
            swy1[i] = w1 * v1;
        } else {
            sxo0[i] = c0 * C_DIM;
            sxo1[i] = c1 * C_DIM;
            swx0[i] = w0 * v0;
            swx1[i] = w1 * v1;
        }
    }
    __syncthreads();

    const int w    = t >> 5;
    const int lane = t & 31;
    const int chBase = blockIdx.y * 128 + w * 32;
    const float* __restrict__ fb = g_featT + chBase + lane;
    float* sm = stage[w];

    for (int py = 0; py < 7; py++) {
        #pragma unroll
        for (int px = 0; px < 7; px++) {
            float m = -3.4e38f;
            #pragma unroll
            for (int dy = 0; dy < 2; dy++) {
                const int sy = 2 * py + dy;
                const int oy0 = syo0[sy], oy1 = syo1[sy];
                const float wy0 = swy0[sy], wy1 = swy1[sy];
                #pragma unroll
                for (int dx = 0; dx < 2; dx++) {
                    const int sx = 2 * px + dx;
                    const int ox0 = sxo0[sx], ox1 = sxo1[sx];
                    const float wx0 = swx0[sx], wx1 = swx1[sx];
                    float f00 = fb[oy0 + ox0];
                    float f01 = fb[oy0 + ox1];
                    float f10 = fb[oy1 + ox0];
                    float f11 = fb[oy1 + ox1];
                    float r0 = f00 * wx0 + f01 * wx1;
                    float r1 = f10 * wx0 + f11 * wx1;
                    float v  = r0 * wy0 + r1 * wy1;
                    m = fmaxf(m, v);
                }
            }
            // layout c*49+p: bank = (lane*49+p)%32 = (lane*17+p)%32, conflict-free
            sm[lane * 49 + py * 7 + px] = m;
        }
    }
    __syncwarp();

    // ---- coalesced writeback: 1568 floats = 12 x float4 warp-stores + 32 tail
    float* ob = out + (size_t)n * (C_DIM * 49) + (size_t)chBase * 49;
    const float4* sm4 = (const float4*)sm;
    float4* ob4 = (float4*)ob;
    #pragma unroll
    for (int k = 0; k < 12; k++)
        ob4[k * 32 + lane] = sm4[k * 32 + lane];
    ob[1536 + lane] = sm[1536 + lane];
}

// -------------------------------------------------------------------------
extern "C" void kernel_launch(void* const* d_in, const int* in_sizes, int n_in,
                              void* d_out, int out_size) {
    const float* bottom = (const float*)d_in[0];
    const float* rois   = (const float*)d_in[1];
    // defensive: identify by size (bottom = 512*50*75 = 1,920,000; rois = 2560)
    if (n_in >= 2 && in_sizes[0] == NROI * 5) {
        bottom = (const float*)d_in[1];
        rois   = (const float*)d_in[0];
    }
    float* out = (float*)d_out;

    dim3 tgrid((HW_DIM + 31) / 32, C_DIM / 32);
    transpose_kernel<<<tgrid, dim3(32, 8)>>>(bottom);

    dim3 rgrid(NROI, 4);
    roi_pool_kernel<<<rgrid, 128>>>(rois, out);
}

// round 2
// speedup vs baseline: 2.6324x; 2.6324x over previous
#include <cuda_runtime.h>
#include <float.h>

#define C_DIM 512
#define H_DIM 50
#define W_DIM 75
#define HW_DIM (H_DIM * W_DIM)
#define NROI 512
#define PRE 14
#define PADC 132   // stage row stride in floats (33 float4), multiple of 4

// channels-last scratch copy of the feature map: [H*W, C]
__device__ __align__(16) float g_featT[HW_DIM * C_DIM];

// -------------------------------------------------------------------------
// Tiled transpose: bottom [C, H*W] -> g_featT [H*W, C]
// -------------------------------------------------------------------------
__global__ void transpose_kernel(const float* __restrict__ in) {
    __shared__ float tile[32][33];
    int hw0 = blockIdx.x * 32;
    int c0  = blockIdx.y * 32;
    int tx = threadIdx.x, ty = threadIdx.y;

    #pragma unroll
    for (int j = 0; j < 32; j += 8) {
        int hw = hw0 + tx;
        int c  = c0 + ty + j;
        if (hw < HW_DIM) tile[ty + j][tx] = in[c * HW_DIM + hw];
    }
    __syncthreads();
    #pragma unroll
    for (int j = 0; j < 32; j += 8) {
        int hw = hw0 + ty + j;
        int c  = c0 + tx;
        if (hw < HW_DIM) g_featT[hw * C_DIM + c] = tile[tx][ty + j];
    }
}

// -------------------------------------------------------------------------
// Main kernel: grid (512 rois, 4 channel-quarters), 128 threads (4 warps).
// Lane owns 4 consecutive channels (float4); a warp covers the full
// 128-channel quarter; the 4 warps split the 49 output pixels round-robin.
// -------------------------------------------------------------------------
__global__ __launch_bounds__(128, 4) void roi_pool_kernel(
    const float* __restrict__ rois, float* __restrict__ out) {

    // Packed corner tables: (.x = off0 as int bits, .y = off1 as int bits,
    //                        .z = w0, .w = w1), offsets in float4 units.
    __shared__ float4 tabx[PRE], taby[PRE];
    __shared__ __align__(16) float stage[49 * PADC];

    const int n = blockIdx.x;
    const int t = threadIdx.x;

    // ---- per-ROI corner tables (threads 0..27) ----
    if (t < 2 * PRE) {
        const int axis = (t >= PRE);          // 0 = x, 1 = y
        const int i = axis ? (t - PRE) : t;
        const float lo = rois[n * 5 + (axis ? 2 : 1)] * (1.0f / 16.0f);
        const float hi = rois[n * 5 + (axis ? 4 : 3)] * (1.0f / 16.0f);
        const int D = axis ? H_DIM : W_DIM;

        // replicate reference math exactly
        float s  = (hi - lo) / (float)(D - 1);
        float tt = (lo + hi - (float)(D - 1)) / (float)(D - 1);
        float base = -1.0f + (float)i * (2.0f / 13.0f);
        float g  = s * base + tt;
        float xc = (g + 1.0f) * 0.5f * (float)(D - 1);

        float f0 = floorf(xc);
        int   i0 = (int)f0;
        float w1 = xc - f0;
        float w0 = 1.0f - w1;
        float v0 = (i0 >= 0 && i0 <= D - 1) ? 1.0f : 0.0f;
        float v1 = (i0 + 1 >= 0 && i0 + 1 <= D - 1) ? 1.0f : 0.0f;
        int c0 = min(max(i0, 0), D - 1);
        int c1 = min(max(i0 + 1, 0), D - 1);

        // offsets in float4 units of the channels-last layout
        int mul = axis ? (W_DIM * (C_DIM / 4)) : (C_DIM / 4);
        float4 e;
        e.x = __int_as_float(c0 * mul);
        e.y = __int_as_float(c1 * mul);
        e.z = w0 * v0;
        e.w = w1 * v1;
        if (axis) taby[i] = e; else tabx[i] = e;
    }
    __syncthreads();

    const int w    = t >> 5;
    const int lane = t & 31;
    // base pointer for this lane's 4 channels, in float4 units
    const float4* __restrict__ fb =
        (const float4*)g_featT + blockIdx.y * 32 + lane;
    float4* stage4 = (float4*)stage;

    for (int p = w; p < 49; p += 4) {
        const int py = p / 7;
        const int px = p - py * 7;

        const float4 tx0 = tabx[2 * px];
        const float4 tx1 = tabx[2 * px + 1];
        const float4 ty0 = taby[2 * py];
        const float4 ty1 = taby[2 * py + 1];

        float4 m = make_float4(-FLT_MAX, -FLT_MAX, -FLT_MAX, -FLT_MAX);

        #pragma unroll
        for (int dy = 0; dy < 2; dy++) {
            const float4 ty = dy ? ty1 : ty0;
            const int oy0 = __float_as_int(ty.x);
            const int oy1 = __float_as_int(ty.y);
            const float wy0 = ty.z, wy1 = ty.w;
            #pragma unroll
            for (int dx = 0; dx < 2; dx++) {
                const float4 tx = dx ? tx1 : tx0;
                const int ox0 = __float_as_int(tx.x);
                const int ox1 = __float_as_int(tx.y);
                const float wx0 = tx.z, wx1 = tx.w;

                float4 f00 = fb[oy0 + ox0];
                float4 f01 = fb[oy0 + ox1];
                float4 f10 = fb[oy1 + ox0];
                float4 f11 = fb[oy1 + ox1];

                float4 v;
                v.x = (f00.x * wx0 + f01.x * wx1) * wy0 + (f10.x * wx0 + f11.x * wx1) * wy1;
                v.y = (f00.y * wx0 + f01.y * wx1) * wy0 + (f10.y * wx0 + f11.y * wx1) * wy1;
                v.z = (f00.z * wx0 + f01.z * wx1) * wy0 + (f10.z * wx0 + f11.z * wx1) * wy1;
                v.w = (f00.w * wx0 + f01.w * wx1) * wy0 + (f10.w * wx0 + f11.w * wx1) * wy1;
                m.x = fmaxf(m.x, v.x);
                m.y = fmaxf(m.y, v.y);
                m.z = fmaxf(m.z, v.z);
                m.w = fmaxf(m.w, v.w);
            }
        }
        // pixel-major stage: float4 store, lane stride 16B -> conflict-free
        stage4[p * (PADC / 4) + lane] = m;
    }
    __syncthreads();

    // ---- coalesced writeback: 6272 floats, 128 threads x 49 iterations
    // out index idx = c*49 + p walked incrementally (idx = t + k*128)
    float* __restrict__ ob = out + (size_t)n * (C_DIM * 49)
                                 + (size_t)blockIdx.y * (128 * 49);
    int c = t / 49;
    int p = t - c * 49;
    #pragma unroll 7
    for (int k = 0; k < 49; k++) {
        ob[t + k * 128] = stage[p * PADC + c];
        p += 30; c += 2;              // advance by 128 = 2*49 + 30
        if (p >= 49) { p -= 49; c += 1; }
    }
}

// -------------------------------------------------------------------------
extern "C" void kernel_launch(void* const* d_in, const int* in_sizes, int n_in,
                              void* d_out, int out_size) {
    const float* bottom = (const float*)d_in[0];
    const float* rois   = (const float*)d_in[1];
    if (n_in >= 2 && in_sizes[0] == NROI * 5) {
        bottom = (const float*)d_in[1];
        rois   = (const float*)d_in[0];
    }
    float* out = (float*)d_out;

    dim3 tgrid((HW_DIM + 31) / 32, C_DIM / 32);
    transpose_kernel<<<tgrid, dim3(32, 8)>>>(bottom);

    dim3 rgrid(NROI, 4);
    roi_pool_kernel<<<rgrid, 128>>>(rois, out);
}